// round 2
// baseline (speedup 1.0000x reference)
#include <cuda_runtime.h>

// ---------------------------------------------------------------------------
// FCOS head, fp32 direct conv baseline.
// Layer-by-layer conv3x3 (SAME, stride 1) through ping-pong device scratch.
// Block tile: 64 out-channels x (8x8) pixels, 256 threads, 4x4 regs/thread.
// Cin chunked by 16 through shared memory.
// ---------------------------------------------------------------------------

#define KC    16   // cin chunk
#define TCO   64   // cout tile
#define TSP   8    // spatial tile edge
#define IPAD  13   // s_in col pad (conflict-free: 13*r + {0,4} distinct mod 32)
#define WPAD  68   // s_w co pad (mult of 4 -> float4 aligned)

// 16 * 256 * 64 * 64 floats = 64 MiB each
__device__ float g_bufA[16u * 256u * 64u * 64u];
__device__ float g_bufB[16u * 256u * 64u * 64u];

__global__ __launch_bounds__(256)
void conv3x3_k(const float* __restrict__ in,    // [B][256][H][W], image n used
               const float* __restrict__ wgt,   // [coutValid<split part][256][3][3]
               const float* __restrict__ bias,
               const float* __restrict__ wgt2,  // co >= split part (ctr), may be null
               const float* __restrict__ bias2,
               float* __restrict__ out,
               int H, int W, int coutValid, int split, int relu,
               int outMode, int locOff, int chOff)
{
    __shared__ __align__(16) float s_w[KC][9][WPAD];
    __shared__ float s_in[KC][10][IPAD];

    const int tid    = threadIdx.x;
    const int n      = blockIdx.z;
    const int coBase = blockIdx.y * TCO;
    const int tilesX = W / TSP;
    const int tx0    = (blockIdx.x % tilesX) * TSP;
    const int ty0    = (blockIdx.x / tilesX) * TSP;

    const int pid = tid & 15;          // 16 pixel-quads
    const int cog = tid >> 4;          // 16 co-groups of 4
    const int r   = pid >> 1;          // row in tile 0..7
    const int cq  = (pid & 1) * 4;     // col base 0 or 4

    const float* inN = in + (size_t)n * 256 * H * W;

    float acc[4][4];
#pragma unroll
    for (int i = 0; i < 4; i++)
#pragma unroll
        for (int j = 0; j < 4; j++) acc[i][j] = 0.f;

    for (int c0 = 0; c0 < 256; c0 += KC) {
        __syncthreads();
        // ---- load input patch: KC x 10 x 10 (zero-padded borders) ----
        for (int idx = tid; idx < KC * 100; idx += 256) {
            int ci = idx / 100;
            int rr = (idx / 10) % 10;
            int cc = idx % 10;
            int gy = ty0 - 1 + rr;
            int gx = tx0 - 1 + cc;
            float v = 0.f;
            if (gy >= 0 && gy < H && gx >= 0 && gx < W)
                v = inN[(size_t)(c0 + ci) * H * W + gy * W + gx];
            s_in[ci][rr][cc] = v;
        }
        // ---- load weights (gmem-contiguous order), layout [ci][k][co] ----
        for (int idx = tid; idx < TCO * KC * 9; idx += 256) {
            int co  = idx / (KC * 9);
            int rem = idx % (KC * 9);
            int ci  = rem / 9;
            int k   = rem % 9;
            int gco = coBase + co;
            float v = 0.f;
            if (gco < coutValid) {
                const float* wp = (gco < split)
                    ? wgt  + ((size_t)gco * 256 + (c0 + ci)) * 9 + k
                    : wgt2 + ((size_t)(gco - split) * 256 + (c0 + ci)) * 9 + k;
                v = *wp;
            }
            s_w[ci][k][co] = v;
        }
        __syncthreads();

        // ---- compute ----
#pragma unroll 2
        for (int ci = 0; ci < KC; ci++) {
#pragma unroll
            for (int ky = 0; ky < 3; ky++) {
                float rv[6];
#pragma unroll
                for (int j = 0; j < 6; j++) rv[j] = s_in[ci][r + ky][cq + j];
#pragma unroll
                for (int kx = 0; kx < 3; kx++) {
                    const float4 wv =
                        *(const float4*)&s_w[ci][ky * 3 + kx][cog * 4];
#pragma unroll
                    for (int j = 0; j < 4; j++) {
                        acc[0][j] += wv.x * rv[kx + j];
                        acc[1][j] += wv.y * rv[kx + j];
                        acc[2][j] += wv.z * rv[kx + j];
                        acc[3][j] += wv.w * rv[kx + j];
                    }
                }
            }
        }
    }

    // ---- epilogue ----
#pragma unroll
    for (int i = 0; i < 4; i++) {
        int gco = coBase + cog * 4 + i;
        if (gco >= coutValid) continue;
        float b = (gco < split) ? bias[gco] : bias2[gco - split];
#pragma unroll
        for (int j = 0; j < 4; j++) {
            float v = acc[i][j] + b;
            if (relu) v = fmaxf(v, 0.f);
            int y = ty0 + r, x = tx0 + cq + j;
            if (outMode == 0) {
                out[((size_t)n * 256 + gco) * H * W + y * W + x] = v;
            } else {
                // final output: (B, 5376, 85) channels-last
                out[((size_t)n * 5376 + (locOff + (size_t)y * W + x)) * 85
                    + chOff + gco] = v;
            }
        }
    }
}

extern "C" void kernel_launch(void* const* d_in, const int* in_sizes, int n_in,
                              void* d_out, int out_size)
{
    const float* feat[3] = {(const float*)d_in[0], (const float*)d_in[1],
                            (const float*)d_in[2]};
    const float* scw = (const float*)d_in[3];   // stem_cls_w (4,256,256,3,3)
    const float* scb = (const float*)d_in[4];   // stem_cls_b (4,256)
    const float* sbw = (const float*)d_in[5];   // stem_box_w
    const float* sbb = (const float*)d_in[6];   // stem_box_b
    const float* pcw = (const float*)d_in[7];   // pred_cls_w (80,256,3,3)
    const float* pcb = (const float*)d_in[8];
    const float* pbw = (const float*)d_in[9];   // pred_box_w (4,256,3,3)
    const float* pbb = (const float*)d_in[10];
    const float* pqw = (const float*)d_in[11];  // pred_ctr_w (1,256,3,3)
    const float* pqb = (const float*)d_in[12];
    float* out = (float*)d_out;

    float *bufA, *bufB;
    cudaGetSymbolAddress((void**)&bufA, g_bufA);
    cudaGetSymbolAddress((void**)&bufB, g_bufB);

    const int   Hs[3]  = {64, 32, 16};
    const int   loc[3] = {0, 4096, 5120};
    const size_t wstep = 256 * 256 * 9;

    for (int L = 0; L < 3; L++) {
        int H = Hs[L], W = Hs[L];
        dim3 grid((W / TSP) * (H / TSP), 256 / TCO, 16);
        float* dsts[4] = {bufA, bufB, bufA, bufB};

        // ---- cls stem (4 x conv+relu) ----
        const float* src = feat[L];
        for (int i = 0; i < 4; i++) {
            conv3x3_k<<<grid, 256>>>(src, scw + i * wstep, scb + i * 256,
                                     nullptr, nullptr, dsts[i],
                                     H, W, 256, 256, 1, 0, 0, 0);
            src = dsts[i];
        }
        // ---- pred_cls (80 ch) -> out channels [0,80) ----
        dim3 gridc((W / TSP) * (H / TSP), 2, 16);
        conv3x3_k<<<gridc, 256>>>(src, pcw, pcb, nullptr, nullptr,
                                  out, H, W, 80, 80, 0, 1, loc[L], 0);

        // ---- box stem ----
        src = feat[L];
        for (int i = 0; i < 4; i++) {
            conv3x3_k<<<grid, 256>>>(src, sbw + i * wstep, sbb + i * 256,
                                     nullptr, nullptr, dsts[i],
                                     H, W, 256, 256, 1, 0, 0, 0);
            src = dsts[i];
        }
        // ---- pred_box (4) + pred_ctr (1) -> out channels [80,85) ----
        dim3 gridb((W / TSP) * (H / TSP), 1, 16);
        conv3x3_k<<<gridb, 256>>>(src, pbw, pbb, pqw, pqb,
                                  out, H, W, 5, 4, 0, 1, loc[L], 80);
    }
}

// round 4
// speedup vs baseline: 2.7838x; 2.7838x over previous
#include <cuda_runtime.h>
#include <cuda_bf16.h>
#include <stdint.h>

#define ACT_TOT 23904256u      // p3 16*66*66*256 + p4 16*34*34*256 + p5 16*18*18*256
#define WSTR    589824         // 256*9*256
#define SMEMB   (1024 + 131072 + 1024)

__device__ __nv_bfloat16 g_act[6][ACT_TOT];   // planes: Fhi Flo Ahi Alo Bhi Blo
__device__ __nv_bfloat16 g_wb[2][10 * WSTR];  // [hi/lo][slot][co][tap][ci]
__device__ float g_bias[2560];

__device__ __forceinline__ uint32_t smem_u32(const void* p) {
    uint32_t a;
    asm("{ .reg .u64 t; cvta.to.shared.u64 t, %1; cvt.u32.u64 %0, t; }" : "=r"(a) : "l"(p));
    return a;
}
#define SWZ(o) ((o) ^ (((o) >> 3) & 0x70))

#define LDSM4(r, a)                                                            \
    asm volatile("ldmatrix.sync.aligned.m8n8.x4.shared.b16 {%0,%1,%2,%3},[%4];"\
        : "=r"((r)[0]), "=r"((r)[1]), "=r"((r)[2]), "=r"((r)[3]) : "r"(a))

#define MMA(c, a, b)                                                           \
    asm volatile("mma.sync.aligned.m16n8k16.row.col.f32.bf16.bf16.f32 "        \
        "{%0,%1,%2,%3},{%4,%5,%6,%7},{%8,%9},{%0,%1,%2,%3};"                   \
        : "+f"((c)[0]), "+f"((c)[1]), "+f"((c)[2]), "+f"((c)[3])               \
        : "r"((a)[0]), "r"((a)[1]), "r"((a)[2]), "r"((a)[3]),                  \
          "r"((b)[0]), "r"((b)[1]))

#define CPA(d, s) asm volatile("cp.async.cg.shared.global [%0],[%1],16;" :: "r"(d), "l"(s))

// ---------------------------------------------------------------------------
__global__ __launch_bounds__(256, 1)
void conv_tc(const __nv_bfloat16* __restrict__ sH, const __nv_bfloat16* __restrict__ sL,
             const __nv_bfloat16* __restrict__ wH, const __nv_bfloat16* __restrict__ wL,
             const float* __restrict__ bias,
             __nv_bfloat16* __restrict__ dH, __nv_bfloat16* __restrict__ dL,
             float* __restrict__ outF,
             int H, int W, int N, int relu, int mode, int locOff, int chOff, int coValid)
{
    extern __shared__ char raw[];
    const uint32_t raw_u  = smem_u32(raw);
    const uint32_t base_u = (raw_u + 1023) & ~1023u;
    char* const base_c    = raw + (base_u - raw_u);
    float* const s_bias   = (float*)(base_c + 131072);

    const int tid = threadIdx.x, lane = tid & 31;
    const int wm = (tid >> 5) & 1, wn = tid >> 6;   // 2 x 4 warp grid
    const int n = blockIdx.z, coBase = blockIdx.y * 128;
    const int tilesX = W >> 3;
    const int ty0 = (blockIdx.x / tilesX) << 4, tx0 = (blockIdx.x % tilesX) << 3;
    const int Hp = H + 2, Wp = W + 2;

    if (tid < 128) s_bias[tid] = bias[coBase + tid];
    __syncthreads();

    auto loadChunk = [&](int s) {
        const int buf = s & 1, tap = s >> 2, c0 = (s & 3) << 6;
        const int dy = tap / 3, dx = tap % 3;
        const uint32_t tOff = (uint32_t)buf * 65536u;
        if (tid < 128) {
            const int m = tid;
            const size_t pix = ((size_t)n * Hp + (ty0 + (m >> 3) + dy)) * Wp + (tx0 + (m & 7) + dx);
            const char* ah = (const char*)(sH + pix * 256 + c0);
            const char* al = (const char*)(sL + pix * 256 + c0);
#pragma unroll
            for (int j = 0; j < 8; j++) {
                const uint32_t o = SWZ((uint32_t)(m * 128 + j * 16));
                CPA(base_u + tOff + o, ah + j * 16);
                CPA(base_u + tOff + 16384 + o, al + j * 16);
            }
        } else {
            const int r = tid - 128;
            if (r < N) {
                const size_t wo = ((size_t)(coBase + r) * 9 + tap) * 256 + c0;
                const char* bh = (const char*)(wH + wo);
                const char* bl = (const char*)(wL + wo);
#pragma unroll
                for (int j = 0; j < 8; j++) {
                    const uint32_t o = SWZ((uint32_t)(r * 128 + j * 16));
                    CPA(base_u + tOff + 32768 + o, bh + j * 16);
                    CPA(base_u + tOff + 49152 + o, bl + j * 16);
                }
            }
        }
        asm volatile("cp.async.commit_group;" ::: "memory");
    };

    float acc[4][4][4];
#pragma unroll
    for (int i = 0; i < 4; i++)
#pragma unroll
        for (int j = 0; j < 4; j++)
#pragma unroll
            for (int k = 0; k < 4; k++) acc[i][j][k] = 0.f;

    loadChunk(0);
    for (int s = 0; s < 36; s++) {
        if (s < 35) {
            loadChunk(s + 1);
            asm volatile("cp.async.wait_group 1;" ::: "memory");
        } else {
            asm volatile("cp.async.wait_group 0;" ::: "memory");
        }
        __syncthreads();

        const uint32_t tOff = (uint32_t)(s & 1) * 65536u;
#pragma unroll
        for (int kt = 0; kt < 4; kt++) {
            uint32_t ah[4][4], al[4][4], bh[2][4], bl[2][4];
#pragma unroll
            for (int mt = 0; mt < 4; mt++) {
                const int row = wm * 64 + mt * 16 + (lane & 15);
                const int kb  = kt * 32 + ((lane >> 4) << 4);
                const uint32_t ad = base_u + tOff + SWZ((uint32_t)(row * 128 + kb));
                LDSM4(ah[mt], ad);
                LDSM4(al[mt], ad + 16384);
            }
#pragma unroll
            for (int bt = 0; bt < 2; bt++) {
                const int nrow = wn * 32 + bt * 16 + ((lane >> 4) << 3) + (lane & 7);
                const int kb   = kt * 32 + (((lane >> 3) & 1) << 4);
                const uint32_t bd = base_u + tOff + 32768 + SWZ((uint32_t)(nrow * 128 + kb));
                LDSM4(bh[bt], bd);
                LDSM4(bl[bt], bd + 16384);
            }
            // 3 split passes; 16 independent MMAs between accumulator reuses
#pragma unroll
            for (int mt = 0; mt < 4; mt++)
#pragma unroll
                for (int nt = 0; nt < 4; nt++)
                    MMA(acc[mt][nt], ah[mt], (&bh[nt >> 1][(nt & 1) * 2]));
#pragma unroll
            for (int mt = 0; mt < 4; mt++)
#pragma unroll
                for (int nt = 0; nt < 4; nt++)
                    MMA(acc[mt][nt], al[mt], (&bh[nt >> 1][(nt & 1) * 2]));
#pragma unroll
            for (int mt = 0; mt < 4; mt++)
#pragma unroll
                for (int nt = 0; nt < 4; nt++)
                    MMA(acc[mt][nt], ah[mt], (&bl[nt >> 1][(nt & 1) * 2]));
        }
        __syncthreads();
    }

    // ---- epilogue ----
    if (mode == 0) {
#pragma unroll
        for (int mt = 0; mt < 4; mt++)
#pragma unroll
            for (int hf = 0; hf < 2; hf++) {
                const int m = wm * 64 + mt * 16 + hf * 8 + (lane >> 2);
                const size_t pix = ((size_t)n * Hp + (ty0 + (m >> 3) + 1)) * Wp + (tx0 + (m & 7) + 1);
                __nv_bfloat162* oh = (__nv_bfloat162*)(dH + pix * 256 + coBase);
                __nv_bfloat162* ol = (__nv_bfloat162*)(dL + pix * 256 + coBase);
#pragma unroll
                for (int nt = 0; nt < 4; nt++) {
                    const int co = wn * 32 + nt * 8 + (lane & 3) * 2;
                    float v0 = acc[mt][nt][hf * 2 + 0] + s_bias[co];
                    float v1 = acc[mt][nt][hf * 2 + 1] + s_bias[co + 1];
                    if (relu) { v0 = fmaxf(v0, 0.f); v1 = fmaxf(v1, 0.f); }
                    const __nv_bfloat16 h0 = __float2bfloat16(v0), h1 = __float2bfloat16(v1);
                    oh[co >> 1] = __halves2bfloat162(h0, h1);
                    ol[co >> 1] = __halves2bfloat162(
                        __float2bfloat16(v0 - __bfloat162float(h0)),
                        __float2bfloat16(v1 - __bfloat162float(h1)));
                }
            }
    } else {
#pragma unroll
        for (int mt = 0; mt < 4; mt++)
#pragma unroll
            for (int hf = 0; hf < 2; hf++) {
                const int m = wm * 64 + mt * 16 + hf * 8 + (lane >> 2);
                const size_t o = ((size_t)n * 5376 + locOff
                                  + (size_t)(ty0 + (m >> 3)) * W + (tx0 + (m & 7))) * 85 + chOff;
#pragma unroll
                for (int nt = 0; nt < 4; nt++) {
                    const int co = wn * 32 + nt * 8 + (lane & 3) * 2;
                    if (co < coValid)
                        outF[o + co] = acc[mt][nt][hf * 2 + 0] + s_bias[co];
                    if (co + 1 < coValid)
                        outF[o + co + 1] = acc[mt][nt][hf * 2 + 1] + s_bias[co + 1];
                }
            }
    }
}

// ---- NCHW fp32 -> padded NHWC bf16 hi/lo ----
__global__ void prep_feat(const float* __restrict__ src, __nv_bfloat16* __restrict__ dH,
                          __nv_bfloat16* __restrict__ dL, int H, int W)
{
    const int Hp = H + 2, Wp = W + 2;
    const size_t tot = (size_t)16 * Hp * Wp * 256;
    for (size_t t = (size_t)blockIdx.x * blockDim.x + threadIdx.x; t < tot;
         t += (size_t)gridDim.x * blockDim.x) {
        const int c = (int)(t & 255);
        const size_t p = t >> 8;
        const int pix = (int)(p % (Hp * Wp)), n = (int)(p / (Hp * Wp));
        const int yp = pix / Wp, xp = pix % Wp;
        float v = 0.f;
        if (yp >= 1 && yp <= H && xp >= 1 && xp <= W)
            v = src[(((size_t)n * 256 + c) * H + yp - 1) * W + xp - 1];
        const __nv_bfloat16 h = __float2bfloat16(v);
        dH[t] = h;
        dL[t] = __float2bfloat16(v - __bfloat162float(h));
    }
}

// ---- weights [co][ci][3][3] fp32 -> [co][tap][ci] bf16 hi/lo ----
__global__ void prep_w(const float* __restrict__ s, __nv_bfloat16* __restrict__ dH,
                       __nv_bfloat16* __restrict__ dL, int nco)
{
    const int tot = nco * 2304;
    for (int t = blockIdx.x * blockDim.x + threadIdx.x; t < tot; t += gridDim.x * blockDim.x) {
        const int co = t / 2304, r = t - co * 2304, ci = r / 9, tap = r - ci * 9;
        const float v = s[t];
        const __nv_bfloat16 h = __float2bfloat16(v);
        const int d = (co * 9 + tap) * 256 + ci;
        dH[d] = h;
        dL[d] = __float2bfloat16(v - __bfloat162float(h));
    }
}

extern "C" void kernel_launch(void* const* d_in, const int* in_sizes, int n_in,
                              void* d_out, int out_size)
{
    const float* feat[3] = {(const float*)d_in[0], (const float*)d_in[1], (const float*)d_in[2]};
    const float* scw = (const float*)d_in[3];
    const float* scb = (const float*)d_in[4];
    const float* sbw = (const float*)d_in[5];
    const float* sbb = (const float*)d_in[6];
    const float* pcw = (const float*)d_in[7];
    const float* pcb = (const float*)d_in[8];
    const float* pbw = (const float*)d_in[9];
    const float* pbb = (const float*)d_in[10];
    const float* pqw = (const float*)d_in[11];
    const float* pqb = (const float*)d_in[12];
    float* out = (float*)d_out;

    __nv_bfloat16 *act, *wb;
    float* bias;
    cudaGetSymbolAddress((void**)&act, g_act);
    cudaGetSymbolAddress((void**)&wb, g_wb);
    cudaGetSymbolAddress((void**)&bias, g_bias);
    cudaFuncSetAttribute(conv_tc, cudaFuncAttributeMaxDynamicSharedMemorySize, SMEMB);

    __nv_bfloat16* wh = wb;
    __nv_bfloat16* wl = wb + (size_t)10 * WSTR;

    for (int i = 0; i < 4; i++) {
        prep_w<<<1024, 256>>>(scw + (size_t)i * WSTR, wh + (size_t)i * WSTR, wl + (size_t)i * WSTR, 256);
        prep_w<<<1024, 256>>>(sbw + (size_t)i * WSTR, wh + (size_t)(4 + i) * WSTR, wl + (size_t)(4 + i) * WSTR, 256);
    }
    prep_w<<<512, 256>>>(pcw, wh + (size_t)8 * WSTR, wl + (size_t)8 * WSTR, 80);
    prep_w<<<64, 256>>>(pbw, wh + (size_t)9 * WSTR, wl + (size_t)9 * WSTR, 4);
    prep_w<<<64, 256>>>(pqw, wh + (size_t)9 * WSTR + 9216, wl + (size_t)9 * WSTR + 9216, 1);

    cudaMemcpyAsync(bias,        scb, 4096, cudaMemcpyDeviceToDevice);
    cudaMemcpyAsync(bias + 1024, sbb, 4096, cudaMemcpyDeviceToDevice);
    cudaMemcpyAsync(bias + 2048, pcb, 320,  cudaMemcpyDeviceToDevice);
    cudaMemcpyAsync(bias + 2304, pbb, 16,   cudaMemcpyDeviceToDevice);
    cudaMemcpyAsync(bias + 2308, pqb, 4,    cudaMemcpyDeviceToDevice);

    const int Hs[3] = {64, 32, 16};
    const size_t loff[3] = {0u, 17842176u, 22577152u};
    const int loc[3] = {0, 4096, 5120};

    for (int L = 0; L < 3; L++) {
        const int H = Hs[L], W = Hs[L];
        const size_t lo = loff[L];
        __nv_bfloat16* pl[6];
        for (int k = 0; k < 6; k++) pl[k] = act + (size_t)k * ACT_TOT + lo;

        prep_feat<<<4096, 256>>>(feat[L], pl[0], pl[1], H, W);

        dim3 g((H / 16) * (W / 8), 2, 16);
        dim3 gp((H / 16) * (W / 8), 1, 16);
        __nv_bfloat16* rh[5] = {pl[0], pl[2], pl[4], pl[2], pl[4]};
        __nv_bfloat16* rl[5] = {pl[1], pl[3], pl[5], pl[3], pl[5]};

        for (int i = 0; i < 4; i++)
            conv_tc<<<g, 256, SMEMB>>>(rh[i], rl[i], wh + (size_t)i * WSTR, wl + (size_t)i * WSTR,
                                       bias + i * 256, rh[i + 1], rl[i + 1], nullptr,
                                       H, W, 128, 1, 0, 0, 0, 0);
        conv_tc<<<gp, 256, SMEMB>>>(pl[4], pl[5], wh + (size_t)8 * WSTR, wl + (size_t)8 * WSTR,
                                    bias + 2048, nullptr, nullptr, out,
                                    H, W, 80, 0, 1, loc[L], 0, 80);

        for (int i = 0; i < 4; i++)
            conv_tc<<<g, 256, SMEMB>>>(rh[i], rl[i], wh + (size_t)(4 + i) * WSTR, wl + (size_t)(4 + i) * WSTR,
                                       bias + (4 + i) * 256, rh[i + 1], rl[i + 1], nullptr,
                                       H, W, 128, 1, 0, 0, 0, 0);
        conv_tc<<<gp, 256, SMEMB>>>(pl[4], pl[5], wh + (size_t)9 * WSTR, wl + (size_t)9 * WSTR,
                                    bias + 2304, nullptr, nullptr, out,
                                    H, W, 8, 0, 1, loc[L], 80, 5);
    }
}

// round 7
// speedup vs baseline: 3.9639x; 1.4239x over previous
#include <cuda_runtime.h>
#include <cuda_fp16.h>
#include <stdint.h>

#define ACT_TOT 23904256u      // p3 16*66*66*256 + p4 16*34*34*256 + p5 16*18*18*256
#define WSTR    589824         // 256*9*256
#define SMEMB   (1024 + 98304 + 1024)

__device__ __half g_act[6][ACT_TOT];   // planes: Fhi Flo Ahi Alo Bhi Blo
__device__ __half g_w[10 * WSTR];      // [slot][co][tap][ci] fp16
__device__ float  g_bias[2560];

__device__ __forceinline__ uint32_t smem_u32(const void* p) {
    uint32_t a;
    asm("{ .reg .u64 t; cvta.to.shared.u64 t, %1; cvt.u32.u64 %0, t; }" : "=r"(a) : "l"(p));
    return a;
}
#define SWZ(o) ((o) ^ (((o) >> 3) & 0x70))

#define LDSM4(r, a)                                                            \
    asm volatile("ldmatrix.sync.aligned.m8n8.x4.shared.b16 {%0,%1,%2,%3},[%4];"\
        : "=r"((r)[0]), "=r"((r)[1]), "=r"((r)[2]), "=r"((r)[3]) : "r"(a))

#define MMA(c, a, b)                                                           \
    asm volatile("mma.sync.aligned.m16n8k16.row.col.f32.f16.f16.f32 "          \
        "{%0,%1,%2,%3},{%4,%5,%6,%7},{%8,%9},{%0,%1,%2,%3};"                   \
        : "+f"((c)[0]), "+f"((c)[1]), "+f"((c)[2]), "+f"((c)[3])               \
        : "r"((a)[0]), "r"((a)[1]), "r"((a)[2]), "r"((a)[3]),                  \
          "r"((b)[0]), "r"((b)[1]))

#define CPA(d, s) asm volatile("cp.async.cg.shared.global [%0],[%1],16;" :: "r"(d), "l"(s))

// ---------------------------------------------------------------------------
__global__ __launch_bounds__(256, 2)
void conv_tc(const __half* __restrict__ sH, const __half* __restrict__ sL,
             const __half* __restrict__ wgt,
             const float* __restrict__ bias,
             __half* __restrict__ dH, __half* __restrict__ dL,
             float* __restrict__ outF,
             int H, int W, int N, int relu, int mode, int locOff, int chOff, int coValid)
{
    extern __shared__ char raw[];
    const uint32_t raw_u  = smem_u32(raw);
    const uint32_t base_u = (raw_u + 1023) & ~1023u;
    char* const base_c    = raw + (base_u - raw_u);
    float* const s_bias   = (float*)(base_c + 98304);

    const int tid = threadIdx.x, lane = tid & 31;
    const int wm = (tid >> 5) & 1, wn = tid >> 6;   // 2 x 4 warp grid
    const int n = blockIdx.z, coBase = blockIdx.y * 128;
    const int tilesX = W >> 3;
    const int ty0 = (blockIdx.x / tilesX) << 4, tx0 = (blockIdx.x % tilesX) << 3;
    const int Hp = H + 2, Wp = W + 2;

    if (tid < 128) s_bias[tid] = bias[coBase + tid];
    __syncthreads();

    auto loadChunk = [&](int s) {
        const int buf = s & 1, tap = s >> 2, c0 = (s & 3) << 6;
        const int dy = tap / 3, dx = tap % 3;
        const uint32_t tOff = (uint32_t)buf * 49152u;
        if (tid < 128) {
            const int m = tid;
            const size_t pix = ((size_t)n * Hp + (ty0 + (m >> 3) + dy)) * Wp + (tx0 + (m & 7) + dx);
            const char* ah = (const char*)(sH + pix * 256 + c0);
            const char* al = (const char*)(sL + pix * 256 + c0);
#pragma unroll
            for (int j = 0; j < 8; j++) {
                const uint32_t o = SWZ((uint32_t)(m * 128 + j * 16));
                CPA(base_u + tOff + o, ah + j * 16);
                CPA(base_u + tOff + 16384 + o, al + j * 16);
            }
        } else {
            const int r = tid - 128;
            if (r < N) {
                const size_t wo = ((size_t)(coBase + r) * 9 + tap) * 256 + c0;
                const char* bh = (const char*)(wgt + wo);
#pragma unroll
                for (int j = 0; j < 8; j++) {
                    const uint32_t o = SWZ((uint32_t)(r * 128 + j * 16));
                    CPA(base_u + tOff + 32768 + o, bh + j * 16);
                }
            }
        }
        asm volatile("cp.async.commit_group;" ::: "memory");
    };

    float acc[4][4][4];
#pragma unroll
    for (int i = 0; i < 4; i++)
#pragma unroll
        for (int j = 0; j < 4; j++)
#pragma unroll
            for (int k = 0; k < 4; k++) acc[i][j][k] = 0.f;

    loadChunk(0);
    for (int s = 0; s < 36; s++) {
        if (s < 35) {
            loadChunk(s + 1);
            asm volatile("cp.async.wait_group 1;" ::: "memory");
        } else {
            asm volatile("cp.async.wait_group 0;" ::: "memory");
        }
        __syncthreads();

        const uint32_t tOff = (uint32_t)(s & 1) * 49152u;
#pragma unroll
        for (int kt = 0; kt < 4; kt++) {
            uint32_t ah[4][4], al[4][4], bh[2][4];
#pragma unroll
            for (int mt = 0; mt < 4; mt++) {
                const int row = wm * 64 + mt * 16 + (lane & 15);
                const int kb  = kt * 32 + ((lane >> 4) << 4);
                const uint32_t ad = base_u + tOff + SWZ((uint32_t)(row * 128 + kb));
                LDSM4(ah[mt], ad);
                LDSM4(al[mt], ad + 16384);
            }
#pragma unroll
            for (int bt = 0; bt < 2; bt++) {
                const int nrow = wn * 32 + bt * 16 + ((lane >> 4) << 3) + (lane & 7);
                const int kb   = kt * 32 + (((lane >> 3) & 1) << 4);
                const uint32_t bd = base_u + tOff + 32768 + SWZ((uint32_t)(nrow * 128 + kb));
                LDSM4(bh[bt], bd);
            }
            // 2 split passes; 16 independent MMAs between accumulator reuses
#pragma unroll
            for (int mt = 0; mt < 4; mt++)
#pragma unroll
                for (int nt = 0; nt < 4; nt++)
                    MMA(acc[mt][nt], ah[mt], (&bh[nt >> 1][(nt & 1) * 2]));
#pragma unroll
            for (int mt = 0; mt < 4; mt++)
#pragma unroll
                for (int nt = 0; nt < 4; nt++)
                    MMA(acc[mt][nt], al[mt], (&bh[nt >> 1][(nt & 1) * 2]));
        }
        __syncthreads();
    }

    // ---- epilogue ----
    if (mode == 0) {
#pragma unroll
        for (int mt = 0; mt < 4; mt++)
#pragma unroll
            for (int hf = 0; hf < 2; hf++) {
                const int m = wm * 64 + mt * 16 + hf * 8 + (lane >> 2);
                const size_t pix = ((size_t)n * Hp + (ty0 + (m >> 3) + 1)) * Wp + (tx0 + (m & 7) + 1);
                __half2* oh = (__half2*)(dH + pix * 256 + coBase);
                __half2* ol = (__half2*)(dL + pix * 256 + coBase);
#pragma unroll
                for (int nt = 0; nt < 4; nt++) {
                    const int co = wn * 32 + nt * 8 + (lane & 3) * 2;
                    float v0 = acc[mt][nt][hf * 2 + 0] + s_bias[co];
                    float v1 = acc[mt][nt][hf * 2 + 1] + s_bias[co + 1];
                    if (relu) { v0 = fmaxf(v0, 0.f); v1 = fmaxf(v1, 0.f); }
                    const __half h0 = __float2half(v0), h1 = __float2half(v1);
                    oh[co >> 1] = __halves2half2(h0, h1);
                    ol[co >> 1] = __halves2half2(
                        __float2half(v0 - __half2float(h0)),
                        __float2half(v1 - __half2float(h1)));
                }
            }
    } else {
#pragma unroll
        for (int mt = 0; mt < 4; mt++)
#pragma unroll
            for (int hf = 0; hf < 2; hf++) {
                const int m = wm * 64 + mt * 16 + hf * 8 + (lane >> 2);
                const size_t o = ((size_t)n * 5376 + locOff
                                  + (size_t)(ty0 + (m >> 3)) * W + (tx0 + (m & 7))) * 85 + chOff;
#pragma unroll
                for (int nt = 0; nt < 4; nt++) {
                    const int co = wn * 32 + nt * 8 + (lane & 3) * 2;
                    if (co < coValid)
                        outF[o + co] = acc[mt][nt][hf * 2 + 0] + s_bias[co];
                    if (co + 1 < coValid)
                        outF[o + co + 1] = acc[mt][nt][hf * 2 + 1] + s_bias[co + 1];
                }
            }
    }
}

// ---- NCHW fp32 -> padded NHWC fp16 hi/lo ----
__global__ void prep_feat(const float* __restrict__ src, __half* __restrict__ dH,
                          __half* __restrict__ dL, int H, int W)
{
    const int Hp = H + 2, Wp = W + 2;
    const size_t tot = (size_t)16 * Hp * Wp * 256;
    for (size_t t = (size_t)blockIdx.x * blockDim.x + threadIdx.x; t < tot;
         t += (size_t)gridDim.x * blockDim.x) {
        const int c = (int)(t & 255);
        const size_t p = t >> 8;
        const int pix = (int)(p % (Hp * Wp)), n = (int)(p / (Hp * Wp));
        const int yp = pix / Wp, xp = pix % Wp;
        float v = 0.f;
        if (yp >= 1 && yp <= H && xp >= 1 && xp <= W)
            v = src[(((size_t)n * 256 + c) * H + yp - 1) * W + xp - 1];
        const __half h = __float2half(v);
        dH[t] = h;
        dL[t] = __float2half(v - __half2float(h));
    }
}

// ---- weights [co][ci][3][3] fp32 -> [co][tap][ci] fp16 ----
__global__ void prep_w(const float* __restrict__ s, __half* __restrict__ dW, int nco)
{
    const int tot = nco * 2304;
    for (int t = blockIdx.x * blockDim.x + threadIdx.x; t < tot; t += gridDim.x * blockDim.x) {
        const int co = t / 2304, r = t - co * 2304, ci = r / 9, tap = r - ci * 9;
        dW[(co * 9 + tap) * 256 + ci] = __float2half(s[t]);
    }
}

extern "C" void kernel_launch(void* const* d_in, const int* in_sizes, int n_in,
                              void* d_out, int out_size)
{
    const float* feat[3] = {(const float*)d_in[0], (const float*)d_in[1], (const float*)d_in[2]};
    const float* scw = (const float*)d_in[3];
    const float* scb = (const float*)d_in[4];
    const float* sbw = (const float*)d_in[5];
    const float* sbb = (const float*)d_in[6];
    const float* pcw = (const float*)d_in[7];
    const float* pcb = (const float*)d_in[8];
    const float* pbw = (const float*)d_in[9];
    const float* pbb = (const float*)d_in[10];
    const float* pqw = (const float*)d_in[11];
    const float* pqb = (const float*)d_in[12];
    float* out = (float*)d_out;

    __half *act, *wv;
    float* bias;
    cudaGetSymbolAddress((void**)&act, g_act);
    cudaGetSymbolAddress((void**)&wv, g_w);
    cudaGetSymbolAddress((void**)&bias, g_bias);
    cudaFuncSetAttribute(conv_tc, cudaFuncAttributeMaxDynamicSharedMemorySize, SMEMB);

    for (int i = 0; i < 4; i++) {
        prep_w<<<1024, 256>>>(scw + (size_t)i * WSTR, wv + (size_t)i * WSTR, 256);
        prep_w<<<1024, 256>>>(sbw + (size_t)i * WSTR, wv + (size_t)(4 + i) * WSTR, 256);
    }
    prep_w<<<512, 256>>>(pcw, wv + (size_t)8 * WSTR, 80);
    prep_w<<<64, 256>>>(pbw, wv + (size_t)9 * WSTR, 4);
    prep_w<<<64, 256>>>(pqw, wv + (size_t)9 * WSTR + 9216, 1);

    cudaMemcpyAsync(bias,        scb, 4096, cudaMemcpyDeviceToDevice);
    cudaMemcpyAsync(bias + 1024, sbb, 4096, cudaMemcpyDeviceToDevice);
    cudaMemcpyAsync(bias + 2048, pcb, 320,  cudaMemcpyDeviceToDevice);
    cudaMemcpyAsync(bias + 2304, pbb, 16,   cudaMemcpyDeviceToDevice);
    cudaMemcpyAsync(bias + 2308, pqb, 4,    cudaMemcpyDeviceToDevice);

    const int Hs[3] = {64, 32, 16};
    const size_t loff[3] = {0u, 17842176u, 22577152u};
    const int loc[3] = {0, 4096, 5120};

    for (int L = 0; L < 3; L++) {
        const int H = Hs[L], W = Hs[L];
        const size_t lo = loff[L];
        __half* pl[6];
        for (int k = 0; k < 6; k++) pl[k] = act + (size_t)k * ACT_TOT + lo;

        prep_feat<<<4096, 256>>>(feat[L], pl[0], pl[1], H, W);

        dim3 g((H / 16) * (W / 8), 2, 16);
        dim3 gp((H / 16) * (W / 8), 1, 16);
        __half* rh[5] = {pl[0], pl[2], pl[4], pl[2], pl[4]};
        __half* rl[5] = {pl[1], pl[3], pl[5], pl[3], pl[5]};

        for (int i = 0; i < 4; i++)
            conv_tc<<<g, 256, SMEMB>>>(rh[i], rl[i], wv + (size_t)i * WSTR,
                                       bias + i * 256, rh[i + 1], rl[i + 1], nullptr,
                                       H, W, 128, 1, 0, 0, 0, 0);
        conv_tc<<<gp, 256, SMEMB>>>(pl[4], pl[5], wv + (size_t)8 * WSTR,
                                    bias + 2048, nullptr, nullptr, out,
                                    H, W, 80, 0, 1, loc[L], 0, 80);

        for (int i = 0; i < 4; i++)
            conv_tc<<<g, 256, SMEMB>>>(rh[i], rl[i], wv + (size_t)(4 + i) * WSTR,
                                       bias + (4 + i) * 256, rh[i + 1], rl[i + 1], nullptr,
                                       H, W, 128, 1, 0, 0, 0, 0);
        conv_tc<<<gp, 256, SMEMB>>>(pl[4], pl[5], wv + (size_t)9 * WSTR,
                                    bias + 2304, nullptr, nullptr, out,
                                    H, W, 8, 0, 1, loc[L], 80, 5);
    }
}

// round 10
// speedup vs baseline: 6.7537x; 1.7038x over previous
#include <cuda_runtime.h>
#include <cuda_fp16.h>
#include <stdint.h>

#define ACT_TOT 23904256u      // p3 16*66*66*256 + p4 16*34*34*256 + p5 16*18*18*256
#define WSTR    589824         // 256*9*256
#define SMEMB   (1024 + 65536 + 1024)

__device__ __half g_act[3][ACT_TOT];   // planes: F, A, B (padded NHWC fp16)
__device__ __half g_w[10 * WSTR];      // [slot][co][tap][ci] fp16
__device__ float  g_bias[2560];

__device__ __forceinline__ uint32_t smem_u32(const void* p) {
    uint32_t a;
    asm("{ .reg .u64 t; cvta.to.shared.u64 t, %1; cvt.u32.u64 %0, t; }" : "=r"(a) : "l"(p));
    return a;
}
#define SWZ(o) ((o) ^ (((o) >> 3) & 0x70))

#define LDSM4(r, a)                                                            \
    asm volatile("ldmatrix.sync.aligned.m8n8.x4.shared.b16 {%0,%1,%2,%3},[%4];"\
        : "=r"((r)[0]), "=r"((r)[1]), "=r"((r)[2]), "=r"((r)[3]) : "r"(a))

#define MMA(c, a, b)                                                           \
    asm volatile("mma.sync.aligned.m16n8k16.row.col.f32.f16.f16.f32 "          \
        "{%0,%1,%2,%3},{%4,%5,%6,%7},{%8,%9},{%0,%1,%2,%3};"                   \
        : "+f"((c)[0]), "+f"((c)[1]), "+f"((c)[2]), "+f"((c)[3])               \
        : "r"((a)[0]), "r"((a)[1]), "r"((a)[2]), "r"((a)[3]),                  \
          "r"((b)[0]), "r"((b)[1]))

#define CPA(d, s) asm volatile("cp.async.cg.shared.global [%0],[%1],16;" :: "r"(d), "l"(s))

// ---------------------------------------------------------------------------
__global__ __launch_bounds__(256, 2)
void conv_tc(const __half* __restrict__ sH,
             const __half* __restrict__ wgt,
             const float* __restrict__ bias,
             __half* __restrict__ dH,
             float* __restrict__ outF,
             int H, int W, int N, int relu, int mode, int locOff, int chOff, int coValid)
{
    extern __shared__ char raw[];
    const uint32_t raw_u  = smem_u32(raw);
    const uint32_t base_u = (raw_u + 1023) & ~1023u;
    char* const base_c    = raw + (base_u - raw_u);
    float* const s_bias   = (float*)(base_c + 65536);

    const int tid = threadIdx.x, lane = tid & 31;
    const int wm = (tid >> 5) & 1, wn = tid >> 6;   // 2 x 4 warp grid
    const int n = blockIdx.z, coBase = blockIdx.y * 128;
    const int tilesX = W >> 3;
    const int ty0 = (blockIdx.x / tilesX) << 4, tx0 = (blockIdx.x % tilesX) << 3;
    const int Hp = H + 2, Wp = W + 2;

    if (tid < 128) s_bias[tid] = bias[coBase + tid];
    __syncthreads();

    auto loadChunk = [&](int s) {
        const int buf = s & 1, tap = s >> 2, c0 = (s & 3) << 6;
        const int dy = tap / 3, dx = tap % 3;
        const uint32_t tOff = (uint32_t)buf * 32768u;
        if (tid < 128) {
            const int m = tid;
            const size_t pix = ((size_t)n * Hp + (ty0 + (m >> 3) + dy)) * Wp + (tx0 + (m & 7) + dx);
            const char* ah = (const char*)(sH + pix * 256 + c0);
#pragma unroll
            for (int j = 0; j < 8; j++) {
                const uint32_t o = SWZ((uint32_t)(m * 128 + j * 16));
                CPA(base_u + tOff + o, ah + j * 16);
            }
        } else {
            const int r = tid - 128;
            if (r < N) {
                const size_t wo = ((size_t)(coBase + r) * 9 + tap) * 256 + c0;
                const char* bh = (const char*)(wgt + wo);
#pragma unroll
                for (int j = 0; j < 8; j++) {
                    const uint32_t o = SWZ((uint32_t)(r * 128 + j * 16));
                    CPA(base_u + tOff + 16384 + o, bh + j * 16);
                }
            }
        }
        asm volatile("cp.async.commit_group;" ::: "memory");
    };

    float acc[4][4][4];
#pragma unroll
    for (int i = 0; i < 4; i++)
#pragma unroll
        for (int j = 0; j < 4; j++)
#pragma unroll
            for (int k = 0; k < 4; k++) acc[i][j][k] = 0.f;

    loadChunk(0);
    for (int s = 0; s < 36; s++) {
        if (s < 35) {
            loadChunk(s + 1);
            asm volatile("cp.async.wait_group 1;" ::: "memory");
        } else {
            asm volatile("cp.async.wait_group 0;" ::: "memory");
        }
        __syncthreads();

        const uint32_t tOff = (uint32_t)(s & 1) * 32768u;
#pragma unroll
        for (int kt = 0; kt < 4; kt++) {
            uint32_t ah[4][4], bh[2][4];
#pragma unroll
            for (int mt = 0; mt < 4; mt++) {
                const int row = wm * 64 + mt * 16 + (lane & 15);
                const int kb  = kt * 32 + ((lane >> 4) << 4);
                LDSM4(ah[mt], base_u + tOff + SWZ((uint32_t)(row * 128 + kb)));
            }
#pragma unroll
            for (int bt = 0; bt < 2; bt++) {
                const int nrow = wn * 32 + bt * 16 + ((lane >> 4) << 3) + (lane & 7);
                const int kb   = kt * 32 + (((lane >> 3) & 1) << 4);
                LDSM4(bh[bt], base_u + tOff + 16384 + SWZ((uint32_t)(nrow * 128 + kb)));
            }
#pragma unroll
            for (int mt = 0; mt < 4; mt++)
#pragma unroll
                for (int nt = 0; nt < 4; nt++)
                    MMA(acc[mt][nt], ah[mt], (&bh[nt >> 1][(nt & 1) * 2]));
        }
        __syncthreads();
    }

    // ---- epilogue ----
    if (mode == 0) {
#pragma unroll
        for (int mt = 0; mt < 4; mt++)
#pragma unroll
            for (int hf = 0; hf < 2; hf++) {
                const int m = wm * 64 + mt * 16 + hf * 8 + (lane >> 2);
                const size_t pix = ((size_t)n * Hp + (ty0 + (m >> 3) + 1)) * Wp + (tx0 + (m & 7) + 1);
                __half2* oh = (__half2*)(dH + pix * 256 + coBase);
#pragma unroll
                for (int nt = 0; nt < 4; nt++) {
                    const int co = wn * 32 + nt * 8 + (lane & 3) * 2;
                    float v0 = acc[mt][nt][hf * 2 + 0] + s_bias[co];
                    float v1 = acc[mt][nt][hf * 2 + 1] + s_bias[co + 1];
                    if (relu) { v0 = fmaxf(v0, 0.f); v1 = fmaxf(v1, 0.f); }
                    oh[co >> 1] = __halves2half2(__float2half(v0), __float2half(v1));
                }
            }
    } else {
#pragma unroll
        for (int mt = 0; mt < 4; mt++)
#pragma unroll
            for (int hf = 0; hf < 2; hf++) {
                const int m = wm * 64 + mt * 16 + hf * 8 + (lane >> 2);
                const size_t o = ((size_t)n * 5376 + locOff
                                  + (size_t)(ty0 + (m >> 3)) * W + (tx0 + (m & 7))) * 85 + chOff;
#pragma unroll
                for (int nt = 0; nt < 4; nt++) {
                    const int co = wn * 32 + nt * 8 + (lane & 3) * 2;
                    if (co < coValid)
                        outF[o + co] = acc[mt][nt][hf * 2 + 0] + s_bias[co];
                    if (co + 1 < coValid)
                        outF[o + co + 1] = acc[mt][nt][hf * 2 + 1] + s_bias[co + 1];
                }
            }
    }
}

// ---- NCHW fp32 -> padded NHWC fp16 ----
__global__ void prep_feat(const float* __restrict__ src, __half* __restrict__ dH,
                          int H, int W)
{
    const int Hp = H + 2, Wp = W + 2;
    const size_t tot = (size_t)16 * Hp * Wp * 256;
    for (size_t t = (size_t)blockIdx.x * blockDim.x + threadIdx.x; t < tot;
         t += (size_t)gridDim.x * blockDim.x) {
        const int c = (int)(t & 255);
        const size_t p = t >> 8;
        const int pix = (int)(p % (Hp * Wp)), n = (int)(p / (Hp * Wp));
        const int yp = pix / Wp, xp = pix % Wp;
        float v = 0.f;
        if (yp >= 1 && yp <= H && xp >= 1 && xp <= W)
            v = src[(((size_t)n * 256 + c) * H + yp - 1) * W + xp - 1];
        dH[t] = __float2half(v);
    }
}

// ---- weights [co][ci][3][3] fp32 -> [co][tap][ci] fp16 ----
__global__ void prep_w(const float* __restrict__ s, __half* __restrict__ dW, int nco)
{
    const int tot = nco * 2304;
    for (int t = blockIdx.x * blockDim.x + threadIdx.x; t < tot; t += gridDim.x * blockDim.x) {
        const int co = t / 2304, r = t - co * 2304, ci = r / 9, tap = r - ci * 9;
        dW[(co * 9 + tap) * 256 + ci] = __float2half(s[t]);
    }
}

extern "C" void kernel_launch(void* const* d_in, const int* in_sizes, int n_in,
                              void* d_out, int out_size)
{
    const float* feat[3] = {(const float*)d_in[0], (const float*)d_in[1], (const float*)d_in[2]};
    const float* scw = (const float*)d_in[3];
    const float* scb = (const float*)d_in[4];
    const float* sbw = (const float*)d_in[5];
    const float* sbb = (const float*)d_in[6];
    const float* pcw = (const float*)d_in[7];
    const float* pcb = (const float*)d_in[8];
    const float* pbw = (const float*)d_in[9];
    const float* pbb = (const float*)d_in[10];
    const float* pqw = (const float*)d_in[11];
    const float* pqb = (const float*)d_in[12];
    float* out = (float*)d_out;

    __half *act, *wv;
    float* bias;
    cudaGetSymbolAddress((void**)&act, g_act);
    cudaGetSymbolAddress((void**)&wv, g_w);
    cudaGetSymbolAddress((void**)&bias, g_bias);
    cudaFuncSetAttribute(conv_tc, cudaFuncAttributeMaxDynamicSharedMemorySize, SMEMB);

    for (int i = 0; i < 4; i++) {
        prep_w<<<1024, 256>>>(scw + (size_t)i * WSTR, wv + (size_t)i * WSTR, 256);
        prep_w<<<1024, 256>>>(sbw + (size_t)i * WSTR, wv + (size_t)(4 + i) * WSTR, 256);
    }
    prep_w<<<512, 256>>>(pcw, wv + (size_t)8 * WSTR, 80);
    prep_w<<<64, 256>>>(pbw, wv + (size_t)9 * WSTR, 4);
    prep_w<<<64, 256>>>(pqw, wv + (size_t)9 * WSTR + 9216, 1);

    cudaMemcpyAsync(bias,        scb, 4096, cudaMemcpyDeviceToDevice);
    cudaMemcpyAsync(bias + 1024, sbb, 4096, cudaMemcpyDeviceToDevice);
    cudaMemcpyAsync(bias + 2048, pcb, 320,  cudaMemcpyDeviceToDevice);
    cudaMemcpyAsync(bias + 2304, pbb, 16,   cudaMemcpyDeviceToDevice);
    cudaMemcpyAsync(bias + 2308, pqb, 4,    cudaMemcpyDeviceToDevice);

    const int Hs[3] = {64, 32, 16};
    const size_t loff[3] = {0u, 17842176u, 22577152u};
    const int loc[3] = {0, 4096, 5120};

    for (int L = 0; L < 3; L++) {
        const int H = Hs[L], W = Hs[L];
        const size_t lo = loff[L];
        __half* pl[3];
        for (int k = 0; k < 3; k++) pl[k] = act + (size_t)k * ACT_TOT + lo;

        prep_feat<<<2048, 256>>>(feat[L], pl[0], H, W);

        dim3 g((H / 16) * (W / 8), 2, 16);
        dim3 gp((H / 16) * (W / 8), 1, 16);
        __half* rsrc[5] = {pl[0], pl[1], pl[2], pl[1], pl[2]};

        for (int i = 0; i < 4; i++)
            conv_tc<<<g, 256, SMEMB>>>(rsrc[i], wv + (size_t)i * WSTR,
                                       bias + i * 256, rsrc[i + 1], nullptr,
                                       H, W, 128, 1, 0, 0, 0, 0);
        conv_tc<<<gp, 256, SMEMB>>>(pl[2], wv + (size_t)8 * WSTR,
                                    bias + 2048, nullptr, out,
                                    H, W, 80, 0, 1, loc[L], 0, 80);

        for (int i = 0; i < 4; i++)
            conv_tc<<<g, 256, SMEMB>>>(rsrc[i], wv + (size_t)(4 + i) * WSTR,
                                       bias + (4 + i) * 256, rsrc[i + 1], nullptr,
                                       H, W, 128, 1, 0, 0, 0, 0);
        conv_tc<<<gp, 256, SMEMB>>>(pl[2], wv + (size_t)9 * WSTR,
                                    bias + 2304, nullptr, out,
                                    H, W, 8, 0, 1, loc[L], 80, 5);
    }
}

// round 13
// speedup vs baseline: 8.0198x; 1.1875x over previous
#include <cuda_runtime.h>
#include <cuda_fp16.h>
#include <stdint.h>

#define ACT_TOT 23904256u      // p3 16*66*66*256 + p4 16*34*34*256 + p5 16*18*18*256
#define WSTR    589824         // 256*9*256
#define SMEMB   (1024 + 65536 + 1024)
#define LOFF1   17842176u
#define LOFF2   22577152u

// planes: 0=F, 1=A_cls, 2=B_cls, 3=A_box, 4=B_box  (padded NHWC fp16)
__device__ __half g_act[5][ACT_TOT];
__device__ __half g_w[10 * WSTR];      // [slot][co][tap][ci]; slots 0-3 cls stem, 4-7 box stem, 8 cls pred, 9 box+ctr pred
__device__ float  g_bias[2560];

__device__ __forceinline__ uint32_t smem_u32(const void* p) {
    uint32_t a;
    asm("{ .reg .u64 t; cvta.to.shared.u64 t, %1; cvt.u32.u64 %0, t; }" : "=r"(a) : "l"(p));
    return a;
}
#define SWZ(o) ((o) ^ (((o) >> 3) & 0x70))

#define LDSM4(r, a)                                                            \
    asm volatile("ldmatrix.sync.aligned.m8n8.x4.shared.b16 {%0,%1,%2,%3},[%4];"\
        : "=r"((r)[0]), "=r"((r)[1]), "=r"((r)[2]), "=r"((r)[3]) : "r"(a))

#define MMA(c, a, b)                                                           \
    asm volatile("mma.sync.aligned.m16n8k16.row.col.f32.f16.f16.f32 "          \
        "{%0,%1,%2,%3},{%4,%5,%6,%7},{%8,%9},{%0,%1,%2,%3};"                   \
        : "+f"((c)[0]), "+f"((c)[1]), "+f"((c)[2]), "+f"((c)[3])               \
        : "r"((a)[0]), "r"((a)[1]), "r"((a)[2]), "r"((a)[3]),                  \
          "r"((b)[0]), "r"((b)[1]))

#define CPA(d, s) asm volatile("cp.async.cg.shared.global [%0],[%1],16;" :: "r"(d), "l"(s))

// ---------------------------------------------------------------------------
// Merged conv: one launch covers all 3 levels (blockIdx.x tile table),
// both branches and (for stems) both co-halves via blockIdx.y.
//   mode 0 (stem layer `layer`): y = branch*2 + coHalf
//   mode 1 (preds):              y = branch (0=cls N=80, 1=box+ctr N=5)
// ---------------------------------------------------------------------------
__global__ __launch_bounds__(256, 2)
void conv_tc(const __half* __restrict__ actBase,
             const __half* __restrict__ wv,
             const float* __restrict__ biasAll,
             float* __restrict__ outF,
             int layer, int mode)
{
    extern __shared__ char raw[];
    const uint32_t raw_u  = smem_u32(raw);
    const uint32_t base_u = (raw_u + 1023) & ~1023u;
    char* const base_c    = raw + (base_u - raw_u);
    float* const s_bias   = (float*)(base_c + 65536);

    const int tid = threadIdx.x, lane = tid & 31;
    const int wm = (tid >> 5) & 1, wn = tid >> 6;   // 2 x 4 warp grid
    const int n = blockIdx.z;

    // ---- decode level & tile ----
    const int bx = blockIdx.x;
    int L, tile;
    if (bx < 32)      { L = 0; tile = bx; }
    else if (bx < 40) { L = 1; tile = bx - 32; }
    else              { L = 2; tile = bx - 40; }
    const int H = 64 >> L, W = H;
    const int Hp = H + 2, Wp = W + 2;
    const size_t lo = (L == 0) ? 0u : (L == 1 ? LOFF1 : LOFF2);
    const int locOff = (L == 0) ? 0 : (L == 1 ? 4096 : 5120);

    // ---- decode branch / co-half, resolve pointers ----
    int branch, coBase, N, relu, chOff, coValid;
    const __half *src, *wgt;
    __half* dst;
    const float* bias;
    if (mode == 0) {
        branch = blockIdx.y >> 1;
        coBase = (blockIdx.y & 1) << 7;
        const int a = 1 + branch * 2, b = 2 + branch * 2;
        // chain F->a->b->a->b : src {0,a,b,a}, dst {a,b,a,b}
        const int sp2 = (layer == 0) ? 0 : ((layer == 1 || layer == 3) ? a : b);
        const int dp2 = (layer == 0 || layer == 2) ? a : b;
        src = actBase + (size_t)sp2 * ACT_TOT + lo;
        dst = (__half*)actBase + (size_t)dp2 * ACT_TOT + lo;
        wgt = wv + (size_t)(branch * 4 + layer) * WSTR;
        bias = biasAll + (branch * 4 + layer) * 256;
        N = 128; relu = 1; chOff = 0; coValid = 128;
    } else {
        branch = blockIdx.y;
        coBase = 0;
        src = actBase + (size_t)(2 + branch * 2) * ACT_TOT + lo;  // cls:B_cls, box:B_box
        dst = nullptr;
        wgt = wv + (size_t)(8 + branch) * WSTR;
        bias = biasAll + (branch ? 2304 : 2048);
        N = branch ? 8 : 80; relu = 0; chOff = branch ? 80 : 0; coValid = branch ? 5 : 80;
    }

    const int tilesX = W >> 3;
    const int ty0 = (tile / tilesX) << 4, tx0 = (tile % tilesX) << 3;

    if (tid < 128) s_bias[tid] = bias[coBase + tid];
    __syncthreads();

    auto loadChunk = [&](int s) {
        const int buf = s & 1, tap = s >> 2, c0 = (s & 3) << 6;
        const int dy = tap / 3, dx = tap % 3;
        const uint32_t tOff = (uint32_t)buf * 32768u;
        if (tid < 128) {
            const int m = tid;
            const size_t pix = ((size_t)n * Hp + (ty0 + (m >> 3) + dy)) * Wp + (tx0 + (m & 7) + dx);
            const char* ah = (const char*)(src + pix * 256 + c0);
#pragma unroll
            for (int j = 0; j < 8; j++) {
                const uint32_t o = SWZ((uint32_t)(m * 128 + j * 16));
                CPA(base_u + tOff + o, ah + j * 16);
            }
        } else {
            const int r = tid - 128;
            if (r < N) {
                const size_t wo = ((size_t)(coBase + r) * 9 + tap) * 256 + c0;
                const char* bh = (const char*)(wgt + wo);
#pragma unroll
                for (int j = 0; j < 8; j++) {
                    const uint32_t o = SWZ((uint32_t)(r * 128 + j * 16));
                    CPA(base_u + tOff + 16384 + o, bh + j * 16);
                }
            }
        }
        asm volatile("cp.async.commit_group;" ::: "memory");
    };

    float acc[4][4][4];
#pragma unroll
    for (int i = 0; i < 4; i++)
#pragma unroll
        for (int j = 0; j < 4; j++)
#pragma unroll
            for (int k = 0; k < 4; k++) acc[i][j][k] = 0.f;

    loadChunk(0);
    for (int s = 0; s < 36; s++) {
        if (s < 35) {
            loadChunk(s + 1);
            asm volatile("cp.async.wait_group 1;" ::: "memory");
        } else {
            asm volatile("cp.async.wait_group 0;" ::: "memory");
        }
        __syncthreads();

        const uint32_t tOff = (uint32_t)(s & 1) * 32768u;
#pragma unroll
        for (int kt = 0; kt < 4; kt++) {
            uint32_t ah[4][4], bh[2][4];
#pragma unroll
            for (int mt = 0; mt < 4; mt++) {
                const int row = wm * 64 + mt * 16 + (lane & 15);
                const int kb  = kt * 32 + ((lane >> 4) << 4);
                LDSM4(ah[mt], base_u + tOff + SWZ((uint32_t)(row * 128 + kb)));
            }
#pragma unroll
            for (int bt = 0; bt < 2; bt++) {
                const int nrow = wn * 32 + bt * 16 + ((lane >> 4) << 3) + (lane & 7);
                const int kb   = kt * 32 + (((lane >> 3) & 1) << 4);
                LDSM4(bh[bt], base_u + tOff + 16384 + SWZ((uint32_t)(nrow * 128 + kb)));
            }
#pragma unroll
            for (int mt = 0; mt < 4; mt++)
#pragma unroll
                for (int nt = 0; nt < 4; nt++)
                    MMA(acc[mt][nt], ah[mt], (&bh[nt >> 1][(nt & 1) * 2]));
        }
        __syncthreads();
    }

    // ---- epilogue ----
    if (mode == 0) {
#pragma unroll
        for (int mt = 0; mt < 4; mt++)
#pragma unroll
            for (int hf = 0; hf < 2; hf++) {
                const int m = wm * 64 + mt * 16 + hf * 8 + (lane >> 2);
                const size_t pix = ((size_t)n * Hp + (ty0 + (m >> 3) + 1)) * Wp + (tx0 + (m & 7) + 1);
                __half2* oh = (__half2*)(dst + pix * 256 + coBase);
#pragma unroll
                for (int nt = 0; nt < 4; nt++) {
                    const int co = wn * 32 + nt * 8 + (lane & 3) * 2;
                    float v0 = fmaxf(acc[mt][nt][hf * 2 + 0] + s_bias[co], 0.f);
                    float v1 = fmaxf(acc[mt][nt][hf * 2 + 1] + s_bias[co + 1], 0.f);
                    oh[co >> 1] = __halves2half2(__float2half(v0), __float2half(v1));
                }
            }
    } else {
#pragma unroll
        for (int mt = 0; mt < 4; mt++)
#pragma unroll
            for (int hf = 0; hf < 2; hf++) {
                const int m = wm * 64 + mt * 16 + hf * 8 + (lane >> 2);
                const size_t o = ((size_t)n * 5376 + locOff
                                  + (size_t)(ty0 + (m >> 3)) * W + (tx0 + (m & 7))) * 85 + chOff;
#pragma unroll
                for (int nt = 0; nt < 4; nt++) {
                    const int co = wn * 32 + nt * 8 + (lane & 3) * 2;
                    if (co < coValid)
                        outF[o + co] = acc[mt][nt][hf * 2 + 0] + s_bias[co];
                    if (co + 1 < coValid)
                        outF[o + co + 1] = acc[mt][nt][hf * 2 + 1] + s_bias[co + 1];
                }
            }
    }
}

// ---- all levels: NCHW fp32 -> padded NHWC fp16 plane 0 ----
__global__ void prep_feat_all(const float* __restrict__ f0, const float* __restrict__ f1,
                              const float* __restrict__ f2, __half* __restrict__ dstP)
{
    for (size_t t = (size_t)blockIdx.x * blockDim.x + threadIdx.x; t < ACT_TOT;
         t += (size_t)gridDim.x * blockDim.x) {
        const float* src;
        size_t t2;
        int H;
        if (t < LOFF1)      { src = f0; t2 = t;         H = 64; }
        else if (t < LOFF2) { src = f1; t2 = t - LOFF1; H = 32; }
        else                { src = f2; t2 = t - LOFF2; H = 16; }
        const int W = H, Hp = H + 2, Wp = W + 2;
        const int c = (int)(t2 & 255);
        const size_t p = t2 >> 8;
        const int pix = (int)(p % (size_t)(Hp * Wp)), n = (int)(p / (size_t)(Hp * Wp));
        const int yp = pix / Wp, xp = pix % Wp;
        float v = 0.f;
        if (yp >= 1 && yp <= H && xp >= 1 && xp <= W)
            v = src[(((size_t)n * 256 + c) * H + yp - 1) * W + xp - 1];
        dstP[t] = __float2half(v);
    }
}

// ---- all weights fp32 -> [slot][co][tap][ci] fp16, one launch ----
__global__ void prep_w_all(const float* __restrict__ scw, const float* __restrict__ sbw,
                           const float* __restrict__ pcw, const float* __restrict__ pbw,
                           const float* __restrict__ pqw, __half* __restrict__ dW)
{
    const int stemTot = 8 * WSTR;
    const int tot = stemTot + 85 * 2304;
    for (int t = blockIdx.x * blockDim.x + threadIdx.x; t < tot; t += gridDim.x * blockDim.x) {
        const float* src;
        __half* dst;
        int li;
        if (t < stemTot) {
            const int slot = t / WSTR;
            li = t - slot * WSTR;
            src = (slot < 4) ? scw + (size_t)slot * WSTR : sbw + (size_t)(slot - 4) * WSTR;
            dst = dW + (size_t)slot * WSTR;
        } else {
            int u = t - stemTot;
            if (u < 80 * 2304)      { src = pcw; li = u;             dst = dW + (size_t)8 * WSTR; }
            else if (u < 84 * 2304) { src = pbw; li = u - 80 * 2304; dst = dW + (size_t)9 * WSTR; }
            else                    { src = pqw; li = u - 84 * 2304; dst = dW + (size_t)9 * WSTR + 9216; }
        }
        const int co = li / 2304, r = li - co * 2304, ci = r / 9, tap = r - ci * 9;
        dst[(co * 9 + tap) * 256 + ci] = __float2half(src[li]);
    }
}

extern "C" void kernel_launch(void* const* d_in, const int* in_sizes, int n_in,
                              void* d_out, int out_size)
{
    const float* f0  = (const float*)d_in[0];
    const float* f1  = (const float*)d_in[1];
    const float* f2  = (const float*)d_in[2];
    const float* scw = (const float*)d_in[3];
    const float* scb = (const float*)d_in[4];
    const float* sbw = (const float*)d_in[5];
    const float* sbb = (const float*)d_in[6];
    const float* pcw = (const float*)d_in[7];
    const float* pcb = (const float*)d_in[8];
    const float* pbw = (const float*)d_in[9];
    const float* pbb = (const float*)d_in[10];
    const float* pqw = (const float*)d_in[11];
    const float* pqb = (const float*)d_in[12];
    float* out = (float*)d_out;

    __half *act, *wv;
    float* bias;
    cudaGetSymbolAddress((void**)&act, g_act);
    cudaGetSymbolAddress((void**)&wv, g_w);
    cudaGetSymbolAddress((void**)&bias, g_bias);
    cudaFuncSetAttribute(conv_tc, cudaFuncAttributeMaxDynamicSharedMemorySize, SMEMB);

    prep_w_all<<<2048, 256>>>(scw, sbw, pcw, pbw, pqw, wv);
    prep_feat_all<<<8192, 256>>>(f0, f1, f2, act);

    cudaMemcpyAsync(bias,        scb, 4096, cudaMemcpyDeviceToDevice);
    cudaMemcpyAsync(bias + 1024, sbb, 4096, cudaMemcpyDeviceToDevice);
    cudaMemcpyAsync(bias + 2048, pcb, 320,  cudaMemcpyDeviceToDevice);
    cudaMemcpyAsync(bias + 2304, pbb, 16,   cudaMemcpyDeviceToDevice);
    cudaMemcpyAsync(bias + 2308, pqb, 4,    cudaMemcpyDeviceToDevice);

    dim3 gs(42, 4, 16);   // 42 tiles x (branch*2+coHalf) x batch
    dim3 gp(42, 2, 16);   // 42 tiles x branch x batch
    for (int layer = 0; layer < 4; layer++)
        conv_tc<<<gs, 256, SMEMB>>>(act, wv, bias, nullptr, layer, 0);
    conv_tc<<<gp, 256, SMEMB>>>(act, wv, bias, out, 0, 1);
}

// round 15
// speedup vs baseline: 8.4690x; 1.0560x over previous
#include <cuda_runtime.h>
#include <cuda_fp16.h>
#include <stdint.h>

#define ACT_TOT 23904256u      // p3 16*66*66*256 + p4 16*34*34*256 + p5 16*18*18*256
#define WSTR    589824         // 256*9*256
#define SMEMB   (3 * 32768 + 1024)
#define LOFF1   17842176u
#define LOFF2   22577152u

// planes: 0=F, 1=A_cls, 2=B_cls, 3=A_box, 4=B_box  (padded NHWC fp16)
__device__ __half g_act[5][ACT_TOT];
__device__ __half g_w[10 * WSTR];      // [slot][co][tap][ci]; 0-3 cls stem, 4-7 box stem, 8 cls pred, 9 box+ctr pred
__device__ float  g_bias[2560];

__device__ __forceinline__ uint32_t smem_u32(const void* p) {
    uint32_t a;
    asm("{ .reg .u64 t; cvta.to.shared.u64 t, %1; cvt.u32.u64 %0, t; }" : "=r"(a) : "l"(p));
    return a;
}
#define SWZ(o) ((o) ^ (((o) >> 3) & 0x70))

#define LDSM4(r, a)                                                            \
    asm volatile("ldmatrix.sync.aligned.m8n8.x4.shared.b16 {%0,%1,%2,%3},[%4];"\
        : "=r"((r)[0]), "=r"((r)[1]), "=r"((r)[2]), "=r"((r)[3]) : "r"(a))

#define MMA(c, a, b)                                                           \
    asm volatile("mma.sync.aligned.m16n8k16.row.col.f32.f16.f16.f32 "          \
        "{%0,%1,%2,%3},{%4,%5,%6,%7},{%8,%9},{%0,%1,%2,%3};"                   \
        : "+f"((c)[0]), "+f"((c)[1]), "+f"((c)[2]), "+f"((c)[3])               \
        : "r"((a)[0]), "r"((a)[1]), "r"((a)[2]), "r"((a)[3]),                  \
          "r"((b)[0]), "r"((b)[1]))

#define CPA(d, s) asm volatile("cp.async.cg.shared.global [%0],[%1],16;" :: "r"(d), "l"(s))

// ---------------------------------------------------------------------------
// Merged conv, templated on MODE (0 = stem layer, 1 = preds).
//   MODE 0: blockIdx.y = branch*2 + coHalf, N=128, relu, act->act
//   MODE 1: blockIdx.y = branch (0: cls N=80; 1: box+ctr N=5), act->out
// 3-stage cp.async pipeline, one __syncthreads per chunk.
// ---------------------------------------------------------------------------
template <int MODE>
__global__ __launch_bounds__(256, 2)
void conv_tc(const __half* __restrict__ actBase,
             const __half* __restrict__ wv,
             const float* __restrict__ biasAll,
             float* __restrict__ outF,
             int layer)
{
    extern __shared__ char raw[];
    const uint32_t raw_u  = smem_u32(raw);
    const uint32_t base_u = (raw_u + 1023) & ~1023u;
    char* const base_c    = raw + (base_u - raw_u);
    float* const s_bias   = (float*)(base_c + 98304);

    const int tid = threadIdx.x, lane = tid & 31;
    const int wm = (tid >> 5) & 1, wn = tid >> 6;   // 2 x 4 warp grid
    const int n = blockIdx.z;

    // ---- decode level & tile ----
    const int bx = blockIdx.x;
    int L, tile;
    if (bx < 32)      { L = 0; tile = bx; }
    else if (bx < 40) { L = 1; tile = bx - 32; }
    else              { L = 2; tile = bx - 40; }
    const int H = 64 >> L, W = H;
    const int Hp = H + 2, Wp = W + 2;
    const size_t lo = (L == 0) ? 0u : (L == 1 ? LOFF1 : LOFF2);

    // ---- decode branch / co-half, resolve pointers ----
    int branch, coBase, N;
    const __half *src, *wgt;
    __half* dst = nullptr;
    const float* bias;
    if (MODE == 0) {
        branch = blockIdx.y >> 1;
        coBase = (blockIdx.y & 1) << 7;
        const int a = 1 + branch * 2, b = 2 + branch * 2;
        // chain F->a->b->a->b : src {0,a,b,a}, dst {a,b,a,b}
        const int sp2 = (layer == 0) ? 0 : ((layer == 1 || layer == 3) ? a : b);
        const int dp2 = (layer == 0 || layer == 2) ? a : b;
        src = actBase + (size_t)sp2 * ACT_TOT + lo;
        dst = (__half*)actBase + (size_t)dp2 * ACT_TOT + lo;
        wgt = wv + (size_t)(branch * 4 + layer) * WSTR;
        bias = biasAll + (branch * 4 + layer) * 256;
        N = 128;
    } else {
        branch = blockIdx.y;
        coBase = 0;
        src = actBase + (size_t)(2 + branch * 2) * ACT_TOT + lo;  // cls:B_cls, box:B_box
        wgt = wv + (size_t)(8 + branch) * WSTR;
        bias = biasAll + (branch ? 2304 : 2048);
        N = branch ? 8 : 80;
    }

    const int tilesX = W >> 3;
    const int ty0 = (tile / tilesX) << 4, tx0 = (tile % tilesX) << 3;

    if (tid < 128) s_bias[tid] = bias[coBase + tid];

    auto loadChunk = [&](int s) {
        const int stg = s % 3, tap = s >> 2, c0 = (s & 3) << 6;
        const int dy = tap / 3, dx = tap % 3;
        const uint32_t tOff = (uint32_t)stg * 32768u;
        if (tid < 128) {
            const int m = tid;
            const size_t pix = ((size_t)n * Hp + (ty0 + (m >> 3) + dy)) * Wp + (tx0 + (m & 7) + dx);
            const char* ah = (const char*)(src + pix * 256 + c0);
#pragma unroll
            for (int j = 0; j < 8; j++) {
                const uint32_t o = SWZ((uint32_t)(m * 128 + j * 16));
                CPA(base_u + tOff + o, ah + j * 16);
            }
        } else {
            const int r = tid - 128;
            if (r < N) {
                const size_t wo = ((size_t)(coBase + r) * 9 + tap) * 256 + c0;
                const char* bh = (const char*)(wgt + wo);
#pragma unroll
                for (int j = 0; j < 8; j++) {
                    const uint32_t o = SWZ((uint32_t)(r * 128 + j * 16));
                    CPA(base_u + tOff + 16384 + o, bh + j * 16);
                }
            }
        }
        asm volatile("cp.async.commit_group;" ::: "memory");
    };

    float acc[4][4][4];
#pragma unroll
    for (int i = 0; i < 4; i++)
#pragma unroll
        for (int j = 0; j < 4; j++)
#pragma unroll
            for (int k = 0; k < 4; k++) acc[i][j][k] = 0.f;

    loadChunk(0);
    loadChunk(1);
    for (int s = 0; s < 36; s++) {
        if (s < 35)
            asm volatile("cp.async.wait_group 1;" ::: "memory");
        else
            asm volatile("cp.async.wait_group 0;" ::: "memory");
        __syncthreads();                 // all warps done with stage (s-1)%3 reads; stage s%3 data visible
        if (s + 2 < 36) loadChunk(s + 2);   // writes stage (s+2)%3, last read by compute(s-1) — safe

        const uint32_t tOff = (uint32_t)(s % 3) * 32768u;
#pragma unroll
        for (int kt = 0; kt < 4; kt++) {
            uint32_t ah[4][4], bh[2][4];
#pragma unroll
            for (int bt = 0; bt < 2; bt++) {
                const int nrow = wn * 32 + bt * 16 + ((lane >> 4) << 3) + (lane & 7);
                const int kb   = kt * 32 + (((lane >> 3) & 1) << 4);
                LDSM4(bh[bt], base_u + tOff + 16384 + SWZ((uint32_t)(nrow * 128 + kb)));
            }
#pragma unroll
            for (int mt = 0; mt < 4; mt++) {
                const int row = wm * 64 + mt * 16 + (lane & 15);
                const int kb  = kt * 32 + ((lane >> 4) << 4);
                LDSM4(ah[mt], base_u + tOff + SWZ((uint32_t)(row * 128 + kb)));
            }
#pragma unroll
            for (int mt = 0; mt < 4; mt++)
#pragma unroll
                for (int nt = 0; nt < 4; nt++)
                    MMA(acc[mt][nt], ah[mt], (&bh[nt >> 1][(nt & 1) * 2]));
        }
    }

    // ---- epilogue ----
    if (MODE == 0) {
#pragma unroll
        for (int mt = 0; mt < 4; mt++)
#pragma unroll
            for (int hf = 0; hf < 2; hf++) {
                const int m = wm * 64 + mt * 16 + hf * 8 + (lane >> 2);
                const size_t pix = ((size_t)n * Hp + (ty0 + (m >> 3) + 1)) * Wp + (tx0 + (m & 7) + 1);
                __half2* oh = (__half2*)(dst + pix * 256 + coBase);
#pragma unroll
                for (int nt = 0; nt < 4; nt++) {
                    const int co = wn * 32 + nt * 8 + (lane & 3) * 2;
                    float v0 = fmaxf(acc[mt][nt][hf * 2 + 0] + s_bias[co], 0.f);
                    float v1 = fmaxf(acc[mt][nt][hf * 2 + 1] + s_bias[co + 1], 0.f);
                    oh[co >> 1] = __halves2half2(__float2half(v0), __float2half(v1));
                }
            }
    } else {
        const int locOff = (L == 0) ? 0 : (L == 1 ? 4096 : 5120);
        const int chOff = branch ? 80 : 0;
        const int coValid = branch ? 5 : 80;
#pragma unroll
        for (int mt = 0; mt < 4; mt++)
#pragma unroll
            for (int hf = 0; hf < 2; hf++) {
                const int m = wm * 64 + mt * 16 + hf * 8 + (lane >> 2);
                const size_t o = ((size_t)n * 5376 + locOff
                                  + (size_t)(ty0 + (m >> 3)) * W + (tx0 + (m & 7))) * 85 + chOff;
#pragma unroll
                for (int nt = 0; nt < 4; nt++) {
                    const int co = wn * 32 + nt * 8 + (lane & 3) * 2;
                    if (co < coValid)
                        outF[o + co] = acc[mt][nt][hf * 2 + 0] + s_bias[co];
                    if (co + 1 < coValid)
                        outF[o + co + 1] = acc[mt][nt][hf * 2 + 1] + s_bias[co + 1];
                }
            }
    }
}

// ---- all levels: NCHW fp32 -> padded NHWC fp16 plane 0 ----
__global__ void prep_feat_all(const float* __restrict__ f0, const float* __restrict__ f1,
                              const float* __restrict__ f2, __half* __restrict__ dstP)
{
    for (size_t t = (size_t)blockIdx.x * blockDim.x + threadIdx.x; t < ACT_TOT;
         t += (size_t)gridDim.x * blockDim.x) {
        const float* src;
        size_t t2;
        int H;
        if (t < LOFF1)      { src = f0; t2 = t;         H = 64; }
        else if (t < LOFF2) { src = f1; t2 = t - LOFF1; H = 32; }
        else                { src = f2; t2 = t - LOFF2; H = 16; }
        const int W = H, Hp = H + 2, Wp = W + 2;
        const int c = (int)(t2 & 255);
        const size_t p = t2 >> 8;
        const int pix = (int)(p % (size_t)(Hp * Wp)), n = (int)(p / (size_t)(Hp * Wp));
        const int yp = pix / Wp, xp = pix % Wp;
        float v = 0.f;
        if (yp >= 1 && yp <= H && xp >= 1 && xp <= W)
            v = src[(((size_t)n * 256 + c) * H + yp - 1) * W + xp - 1];
        dstP[t] = __float2half(v);
    }
}

// ---- all weights fp32 -> [slot][co][tap][ci] fp16, one launch ----
__global__ void prep_w_all(const float* __restrict__ scw, const float* __restrict__ sbw,
                           const float* __restrict__ pcw, const float* __restrict__ pbw,
                           const float* __restrict__ pqw, __half* __restrict__ dW)
{
    const int stemTot = 8 * WSTR;
    const int tot = stemTot + 85 * 2304;
    for (int t = blockIdx.x * blockDim.x + threadIdx.x; t < tot; t += gridDim.x * blockDim.x) {
        const float* src;
        __half* dst;
        int li;
        if (t < stemTot) {
            const int slot = t / WSTR;
            li = t - slot * WSTR;
            src = (slot < 4) ? scw + (size_t)slot * WSTR : sbw + (size_t)(slot - 4) * WSTR;
            dst = dW + (size_t)slot * WSTR;
        } else {
            int u = t - stemTot;
            if (u < 80 * 2304)      { src = pcw; li = u;             dst = dW + (size_t)8 * WSTR; }
            else if (u < 84 * 2304) { src = pbw; li = u - 80 * 2304; dst = dW + (size_t)9 * WSTR; }
            else                    { src = pqw; li = u - 84 * 2304; dst = dW + (size_t)9 * WSTR + 9216; }
        }
        const int co = li / 2304, r = li - co * 2304, ci = r / 9, tap = r - ci * 9;
        dst[(co * 9 + tap) * 256 + ci] = __float2half(src[li]);
    }
}

extern "C" void kernel_launch(void* const* d_in, const int* in_sizes, int n_in,
                              void* d_out, int out_size)
{
    const float* f0  = (const float*)d_in[0];
    const float* f1  = (const float*)d_in[1];
    const float* f2  = (const float*)d_in[2];
    const float* scw = (const float*)d_in[3];
    const float* scb = (const float*)d_in[4];
    const float* sbw = (const float*)d_in[5];
    const float* sbb = (const float*)d_in[6];
    const float* pcw = (const float*)d_in[7];
    const float* pcb = (const float*)d_in[8];
    const float* pbw = (const float*)d_in[9];
    const float* pbb = (const float*)d_in[10];
    const float* pqw = (const float*)d_in[11];
    const float* pqb = (const float*)d_in[12];
    float* out = (float*)d_out;

    __half *act, *wv;
    float* bias;
    cudaGetSymbolAddress((void**)&act, g_act);
    cudaGetSymbolAddress((void**)&wv, g_w);
    cudaGetSymbolAddress((void**)&bias, g_bias);
    cudaFuncSetAttribute(conv_tc<0>, cudaFuncAttributeMaxDynamicSharedMemorySize, SMEMB);
    cudaFuncSetAttribute(conv_tc<1>, cudaFuncAttributeMaxDynamicSharedMemorySize, SMEMB);

    prep_w_all<<<2048, 256>>>(scw, sbw, pcw, pbw, pqw, wv);
    prep_feat_all<<<8192, 256>>>(f0, f1, f2, act);

    cudaMemcpyAsync(bias,        scb, 4096, cudaMemcpyDeviceToDevice);
    cudaMemcpyAsync(bias + 1024, sbb, 4096, cudaMemcpyDeviceToDevice);
    cudaMemcpyAsync(bias + 2048, pcb, 320,  cudaMemcpyDeviceToDevice);
    cudaMemcpyAsync(bias + 2304, pbb, 16,   cudaMemcpyDeviceToDevice);
    cudaMemcpyAsync(bias + 2308, pqb, 4,    cudaMemcpyDeviceToDevice);

    dim3 gs(42, 4, 16);   // 42 tiles x (branch*2+coHalf) x batch
    dim3 gp(42, 2, 16);   // 42 tiles x branch x batch
    for (int layer = 0; layer < 4; layer++)
        conv_tc<0><<<gs, 256, SMEMB>>>(act, wv, bias, nullptr, layer);
    conv_tc<1><<<gp, 256, SMEMB>>>(act, wv, bias, out, 0);
}